// round 5
// baseline (speedup 1.0000x reference)
#include <cuda_runtime.h>
#include <cuda_bf16.h>
#include <cstdint>

#define T_    4
#define B_    32
#define C_    384
#define HID_  1536
#define HW_   196
#define NPAIR (B_*HW_)        // 6272
#define NROW  (NPAIR*T_)      // 25088
#define CW_   (C_/32)         // 12
#define SPIKE_CAP (1u<<22)
#define FIX_CAP   (1u<<20)

#define ON2   256             // output-channel chunk (bf16)
#define NCH2  (HID_/ON2)      // 6
#define PGU   64              // pairs per unit
#define RPU   (PGU*T_)        // 256 rows per unit
#define NGU   (NPAIR/PGU)     // 98
#define NUNITS (NCH2*NGU)     // 588
#define GTH   512
#define GEMM_CTAS 148
#define LCAP  32
#define DELTA 0.125f

// smem layout for gemm
#define WS_BYTES ((C_+1)*ON2*2)      // 197120 (row C_ = zero sentinel)
#define SL_BYTES (RPU*LCAP*2)        // 16384
#define SC_BYTES (RPU*4)             // 1024
#define SMEM2    (WS_BYTES + SL_BYTES + SC_BYTES + 16)

// ---- static device scratch ----
__device__ float          g_w1t[C_*HID_];          // [c][o] fp32 (exact path)
__device__ float          g_w2t[HID_*C_];
__device__ unsigned short g_list[(size_t)NROW*C_]; // padded to mult-8 with sentinel C_
__device__ int            g_cnt[NROW];
__device__ unsigned       g_spikes[SPIKE_CAP];
__device__ unsigned       g_nspk;
__device__ unsigned       g_fix[FIX_CAP];
__device__ unsigned       g_nfix;
__device__ int            g_unitctr;

// ---------------- K0: both transposes + counter reset ----------------
__global__ void k_transpose_both(const float* __restrict__ w1, const float* __restrict__ w2) {
    if (blockIdx.x == 0 && blockIdx.y == 0 && blockIdx.z == 0 &&
        threadIdx.x == 0 && threadIdx.y == 0) {
        g_nspk = 0u; g_nfix = 0u; g_unitctr = 0;
    }
    const float* in; float* outp; int rows, cols;
    if (blockIdx.z == 0) { in = w1; outp = g_w1t; rows = HID_; cols = C_; }
    else                 { in = w2; outp = g_w2t; rows = C_;  cols = HID_; }
    int bx = blockIdx.x * 32, by = blockIdx.y * 32;
    if (bx >= cols || by >= rows) return;

    __shared__ float tile[32][33];
    int x = bx + threadIdx.x;
    #pragma unroll
    for (int k = 0; k < 32; k += 8) {
        int y = by + threadIdx.y + k;
        if (x < cols && y < rows)
            tile[threadIdx.y + k][threadIdx.x] = in[(size_t)y*cols + x];
    }
    __syncthreads();
    int xo = by + threadIdx.x;
    #pragma unroll
    for (int k = 0; k < 32; k += 8) {
        int yo = bx + threadIdx.y + k;
        if (xo < rows && yo < cols)
            outp[(size_t)yo*rows + xo] = tile[threadIdx.x][threadIdx.y + k];
    }
}

// ---------------- K1: fused PLIF1 + list build ----------------
__global__ __launch_bounds__(384)
void k_plif1_list(const float* __restrict__ x, const float* __restrict__ pw1) {
    __shared__ unsigned smask[128][CW_];
    const int tid  = threadIdx.x;
    const int p    = tid & 31;
    const int cw   = tid >> 5;
    const int pair = blockIdx.x * 32 + p;
    const int b = pair / HW_, hw = pair % HW_;
    const float decay = 1.0f / (1.0f + expf(-pw1[0]));

    unsigned bits[T_] = {0u, 0u, 0u, 0u};
    #pragma unroll 4
    for (int j = 0; j < 32; j++) {
        int c = cw * 32 + j;
        const float* xp = x + ((size_t)b * C_ + c) * HW_ + hw;
        float x0 = __ldg(xp);
        float x1 = __ldg(xp + (size_t)1*B_*C_*HW_);
        float x2 = __ldg(xp + (size_t)2*B_*C_*HW_);
        float x3 = __ldg(xp + (size_t)3*B_*C_*HW_);
        float v = 0.f, h;
        h = v + (x0 - v) * decay; if (h >= 1.0f) { bits[0] |= 1u << j; v = 0.f; } else v = h;
        h = v + (x1 - v) * decay; if (h >= 1.0f) { bits[1] |= 1u << j; v = 0.f; } else v = h;
        h = v + (x2 - v) * decay; if (h >= 1.0f) { bits[2] |= 1u << j; v = 0.f; } else v = h;
        h = v + (x3 - v) * decay; if (h >= 1.0f) { bits[3] |= 1u << j; v = 0.f; } else v = h;
    }
    #pragma unroll
    for (int t = 0; t < T_; t++)
        smask[p * T_ + t][cw] = bits[t];
    __syncthreads();

    const int lane = p;
    for (int r = cw; r < 128; r += CW_) {
        const int grow = blockIdx.x * 128 + r;
        unsigned short* lp = g_list + (size_t)grow * C_;
        int base = 0;
        #pragma unroll
        for (int w = 0; w < CW_; w++) {
            unsigned word = smask[r][w];
            if ((word >> lane) & 1u) {
                int pre = __popc(word & ((1u << lane) - 1u));
                lp[base + pre] = (unsigned short)(w * 32 + lane);
            }
            base += __popc(word);
        }
        int padded = (base + 7) & ~7;
        if (lane < padded - base) lp[base + lane] = (unsigned short)C_;
        if (lane == 0) g_cnt[grow] = base;
    }
}

// ---------------- K2: fused sparse GEMM1 (bf16 smem) + flagged PLIF2 ----------------
__device__ __forceinline__ void lds_v2u64(unsigned addr, unsigned long long& a,
                                          unsigned long long& b) {
    asm("ld.shared.v2.u64 {%0,%1},[%2];" : "=l"(a), "=l"(b) : "r"(addr));
}
__device__ __forceinline__ void addx2(unsigned long long& a, unsigned long long v) {
    asm("add.rn.f32x2 %0, %0, %1;" : "+l"(a) : "l"(v));
}
__device__ __forceinline__ unsigned long long bfpack(unsigned g) {
    // u32 holding bf16 pair {lo,hi} -> packed f32x2 {f32(lo), f32(hi)}
    unsigned lo = g << 16;
    unsigned hi = g & 0xffff0000u;
    return ((unsigned long long)hi << 32) | lo;
}
__device__ __forceinline__ void accv(unsigned long long* s, unsigned wbase, unsigned c) {
    unsigned long long va, vb;
    lds_v2u64(wbase + c * 512u, va, vb);
    addx2(s[0], bfpack((unsigned)va));
    addx2(s[1], bfpack((unsigned)(va >> 32)));
    addx2(s[2], bfpack((unsigned)vb));
    addx2(s[3], bfpack((unsigned)(vb >> 32)));
}

__global__ __launch_bounds__(GTH, 1)
void k_gemm1_plif2(const float* __restrict__ pw2, const float* __restrict__ b1) {
    extern __shared__ char sm[];
    __nv_bfloat162* ws   = (__nv_bfloat162*)sm;                       // [(C_+1)][ON2] bf16
    unsigned short* slist = (unsigned short*)(sm + WS_BYTES);         // [RPU][LCAP]
    int*            scnt  = (int*)(sm + WS_BYTES + SL_BYTES);         // [RPU]
    int*            s_u   = (int*)(sm + WS_BYTES + SL_BYTES + SC_BYTES);

    const int tid  = threadIdx.x;
    const int warp = tid >> 5, oq = tid & 31;
    const unsigned wbase = (unsigned)__cvta_generic_to_shared(ws) + oq * 16u;
    const float decay = 1.0f / (1.0f + expf(-pw2[0]));

    int cur = -1;
    float b1r[8];

    for (;;) {
        __syncthreads();                  // previous unit's compute done
        if (tid == 0) *s_u = atomicAdd(&g_unitctr, 1);
        __syncthreads();
        const int u = *s_u;
        if (u >= NUNITS) break;
        const int chunk = u / NGU;
        const int grp   = u - chunk * NGU;

        if (chunk != cur) {
            cur = chunk;
            const float* wp = g_w1t + chunk * ON2;
            for (int i = tid; i < (C_ + 1) * (ON2/4); i += GTH) {
                int c  = i >> 6;          // ON2/4 = 64
                int o4 = i & 63;
                float4 f = (c < C_) ? __ldg((const float4*)(wp + (size_t)c * HID_) + o4)
                                    : make_float4(0.f, 0.f, 0.f, 0.f);
                ws[i*2]   = __floats2bfloat162_rn(f.x, f.y);
                ws[i*2+1] = __floats2bfloat162_rn(f.z, f.w);
            }
            const float4* bp = (const float4*)(b1 + chunk * ON2);
            float4 ba = __ldg(bp + oq*2), bb = __ldg(bp + oq*2 + 1);
            b1r[0]=ba.x; b1r[1]=ba.y; b1r[2]=ba.z; b1r[3]=ba.w;
            b1r[4]=bb.x; b1r[5]=bb.y; b1r[6]=bb.z; b1r[7]=bb.w;
        }

        {   // stage lists (32 entries = 64B per row) + counts
            const uint4* gl4 = (const uint4*)(g_list + (size_t)grp * RPU * C_);
            uint4*       sl4 = (uint4*)slist;
            for (int i = tid; i < RPU * 4; i += GTH) {
                int r = i >> 2, q = i & 3;
                sl4[i] = gl4[(size_t)r * (C_/8) + q];
            }
            if (tid < RPU) scnt[tid] = g_cnt[grp * RPU + tid];
        }
        __syncthreads();

        #pragma unroll
        for (int p = 0; p < 4; p++) {
            const int lpair = warp * 4 + p;           // 0..63
            const int pair  = grp * PGU + lpair;

            unsigned long long A[T_][4];
            #pragma unroll
            for (int t = 0; t < T_; t++)
                #pragma unroll
                for (int j = 0; j < 4; j++) A[t][j] = 0ull;

            #pragma unroll
            for (int t = 0; t < T_; t++) {
                const int lr = lpair * T_ + t;
                const int n  = scnt[lr];
                const uint4* lp = (const uint4*)(slist + lr * LCAP);
                const int nc = n < LCAP ? n : LCAP;
                const int trips = (nc + 7) >> 3;
                unsigned long long* s = A[t];
                for (int q = 0; q < trips; q++) {
                    uint4 L = lp[q];                  // broadcast LDS
                    accv(s, wbase, L.x & 0xffffu);
                    accv(s, wbase, L.x >> 16);
                    accv(s, wbase, L.y & 0xffffu);
                    accv(s, wbase, L.y >> 16);
                    accv(s, wbase, L.z & 0xffffu);
                    accv(s, wbase, L.z >> 16);
                    accv(s, wbase, L.w & 0xffffu);
                    accv(s, wbase, L.w >> 16);
                }
                if (n > LCAP) {                        // rare tail
                    const unsigned short* gp = g_list + (size_t)(grp * RPU + lr) * C_;
                    for (int j = LCAP; j < n; j++)
                        accv(s, wbase, (unsigned)gp[j]);
                }
            }

            // epilogue: PLIF2 with certified flagging
            const int b = pair / HW_, hw = pair % HW_;
            #pragma unroll
            for (int j = 0; j < 8; j++) {
                const int o = chunk * ON2 + oq * 8 + j;
                float v = 0.f;
                bool flag = false;
                int sb = 0;
                #pragma unroll
                for (int t = 0; t < T_; t++) {
                    unsigned long long aw = A[t][j >> 1];
                    float a = __uint_as_float((j & 1) ? (unsigned)(aw >> 32)
                                                      : (unsigned)aw);
                    float xx = a + b1r[j];
                    float h = v + (xx - v) * decay;
                    flag |= (fabsf(h - 1.0f) < DELTA);
                    if (h >= 1.0f) { sb |= 1 << t; v = 0.f; } else v = h;
                }
                if (flag) {
                    unsigned pos = atomicAdd(&g_nfix, 1u);
                    if (pos < FIX_CAP) g_fix[pos] = ((unsigned)pair << 11) | (unsigned)o;
                } else if (sb) {
                    #pragma unroll
                    for (int t = 0; t < T_; t++) if ((sb >> t) & 1) {
                        unsigned pos = atomicAdd(&g_nspk, 1u);
                        if (pos < SPIKE_CAP)
                            g_spikes[pos] = (unsigned)((((t * B_ + b) * HID_) + o) * HW_ + hw);
                    }
                }
            }
        }
    }
}

// ---------------- K3: exact fp32 fixup for flagged elements ----------------
__global__ void k_fixup(const float* __restrict__ pw2, const float* __restrict__ b1) {
    unsigned n = *(volatile unsigned*)&g_nfix;
    if (n > FIX_CAP) n = FIX_CAP;
    const float decay = 1.0f / (1.0f + expf(-pw2[0]));
    for (unsigned i = blockIdx.x * blockDim.x + threadIdx.x; i < n;
         i += gridDim.x * blockDim.x) {
        unsigned e = g_fix[i];
        int pair = e >> 11;
        int o    = e & 2047;
        int b = pair / HW_, hw = pair % HW_;
        float bb = __ldg(b1 + o);
        float v = 0.f;
        #pragma unroll
        for (int t = 0; t < T_; t++) {
            int row = pair * T_ + t;
            int cnt = g_cnt[row];
            const unsigned short* lp = g_list + (size_t)row * C_;
            float s = 0.f;
            for (int j = 0; j < cnt; j++)
                s += __ldg(g_w1t + (size_t)lp[j] * HID_ + o);
            float xx = s + bb;
            float h = v + (xx - v) * decay;
            if (h >= 1.0f) {
                unsigned pos = atomicAdd(&g_nspk, 1u);
                if (pos < SPIKE_CAP)
                    g_spikes[pos] = (unsigned)((((t * B_ + b) * HID_) + o) * HW_ + hw);
                v = 0.f;
            } else v = h;
        }
    }
}

// ---------------- K4: out = b2 ----------------
__global__ __launch_bounds__(256)
void k_outinit(float* __restrict__ out, const float* __restrict__ b2) {
    const int total4 = T_ * B_ * C_ * HW_ / 4;
    int base = (blockIdx.x * blockDim.x + threadIdx.x) * 2;
    #pragma unroll
    for (int k = 0; k < 2; k++) {
        int idx = base + k;
        if (idx < total4) {
            int o = (idx / (HW_ / 4)) % C_;
            float bv = __ldg(b2 + o);
            ((float4*)out)[idx] = make_float4(bv, bv, bv, bv);
        }
    }
}

// ---------------- K5: scatter spikes ----------------
__global__ void k_scatter(float* __restrict__ out) {
    unsigned n = *(volatile unsigned*)&g_nspk;
    if (n > SPIKE_CAP) n = SPIKE_CAP;
    int wid  = (blockIdx.x * blockDim.x + threadIdx.x) >> 5;
    int lane = threadIdx.x & 31;
    int nw   = (gridDim.x * blockDim.x) >> 5;
    for (unsigned s = wid; s < n; s += nw) {
        unsigned lin = g_spikes[s];
        unsigned hw = lin % HW_;
        unsigned r  = lin / HW_;
        unsigned c  = r % HID_;
        unsigned tb = r / HID_;
        const float* wcol = g_w2t + (size_t)c * C_;
        float* op = out + (size_t)tb * C_ * HW_ + hw;
        for (int o = lane; o < C_; o += 32)
            atomicAdd(op + (size_t)o * HW_, wcol[o]);
    }
}

// ---------------- launch ----------------
extern "C" void kernel_launch(void* const* d_in, const int* in_sizes, int n_in,
                              void* d_out, int out_size) {
    const float* x   = (const float*)d_in[0];
    const float* pw1 = (const float*)d_in[1];
    const float* w1  = (const float*)d_in[2];
    const float* b1  = (const float*)d_in[3];
    const float* pw2 = (const float*)d_in[4];
    const float* w2  = (const float*)d_in[5];
    const float* b2  = (const float*)d_in[6];
    float* out = (float*)d_out;
    (void)in_sizes; (void)n_in; (void)out_size;

    cudaFuncSetAttribute(k_gemm1_plif2,
                         cudaFuncAttributeMaxDynamicSharedMemorySize, SMEM2);

    {   // both transposes + counter reset
        dim3 blk(32, 8), grd(48, 48, 2);
        k_transpose_both<<<grd, blk>>>(w1, w2);
    }

    k_plif1_list<<<NPAIR / 32, 384>>>(x, pw1);

    k_gemm1_plif2<<<GEMM_CTAS, GTH, SMEM2>>>(pw2, b1);

    k_fixup<<<4, 256>>>(pw2, b1);

    const int total4 = T_ * B_ * C_ * HW_ / 4;
    k_outinit<<<(total4 / 2 + 255) / 256, 256>>>(out, b2);
    k_scatter<<<256, 256>>>(out);
}

// round 7
// speedup vs baseline: 1.0623x; 1.0623x over previous
#include <cuda_runtime.h>
#include <cuda_bf16.h>
#include <cstdint>
#include <cstring>

#define T_    4
#define B_    32
#define C_    384
#define HID_  1536
#define HW_   196
#define NPAIR (B_*HW_)        // 6272
#define NROW  (NPAIR*T_)      // 25088
#define CW_   (C_/32)         // 12
#define SPIKE_CAP (1u<<22)
#define FIX_CAP   (1u<<20)

#define ON    128             // output-channel chunk (bf16 smem tile)
#define NCH   (HID_/ON)       // 12
#define PG    64              // pairs per group
#define RPG   (PG*T_)         // 256 rows per group
#define NG    (NPAIR/PG)      // 98
#define GSPLIT 12             // 12x12 = 144 CTAs = one wave
#define LCAP  64
#define DELTA 0.125f

#define WS_BYTES ((C_+1)*ON*2)     // 98560 (row C_ = zero sentinel)
#define SL_BYTES (RPG*LCAP*2)      // 32768
#define SC_BYTES (RPG*4)           // 1024
#define SMEM2    (WS_BYTES + SL_BYTES + SC_BYTES)   // 132352

// ---- static device scratch ----
__device__ float          g_w1t[C_*HID_];          // [c][o] fp32 (exact path)
__device__ float          g_w2t[HID_*C_];
__device__ unsigned short g_list[(size_t)NROW*C_]; // padded to mult-8 with sentinel C_
__device__ int            g_cnt[NROW];
__device__ unsigned       g_spikes[SPIKE_CAP];
__device__ unsigned       g_nspk;
__device__ unsigned       g_fix[FIX_CAP];
__device__ unsigned       g_nfix;

// ---------------- K0: both transposes + counter reset ----------------
__global__ void k_transpose_both(const float* __restrict__ w1, const float* __restrict__ w2) {
    if (blockIdx.x == 0 && blockIdx.y == 0 && blockIdx.z == 0 &&
        threadIdx.x == 0 && threadIdx.y == 0) {
        g_nspk = 0u; g_nfix = 0u;
    }
    const float* in; float* outp; int rows, cols;
    if (blockIdx.z == 0) { in = w1; outp = g_w1t; rows = HID_; cols = C_; }
    else                 { in = w2; outp = g_w2t; rows = C_;  cols = HID_; }
    int bx = blockIdx.x * 32, by = blockIdx.y * 32;
    if (bx >= cols || by >= rows) return;

    __shared__ float tile[32][33];
    int x = bx + threadIdx.x;
    #pragma unroll
    for (int k = 0; k < 32; k += 8) {
        int y = by + threadIdx.y + k;
        if (x < cols && y < rows)
            tile[threadIdx.y + k][threadIdx.x] = in[(size_t)y*cols + x];
    }
    __syncthreads();
    int xo = by + threadIdx.x;
    #pragma unroll
    for (int k = 0; k < 32; k += 8) {
        int yo = bx + threadIdx.y + k;
        if (xo < rows && yo < cols)
            outp[(size_t)yo*rows + xo] = tile[threadIdx.x][threadIdx.y + k];
    }
}

// ---------------- K1: fused PLIF1 + list build ----------------
__global__ __launch_bounds__(384)
void k_plif1_list(const float* __restrict__ x, const float* __restrict__ pw1) {
    __shared__ unsigned smask[128][CW_];
    const int tid  = threadIdx.x;
    const int p    = tid & 31;
    const int cw   = tid >> 5;
    const int pair = blockIdx.x * 32 + p;
    const int b = pair / HW_, hw = pair % HW_;
    const float decay = 1.0f / (1.0f + expf(-pw1[0]));

    unsigned bits[T_] = {0u, 0u, 0u, 0u};
    #pragma unroll 4
    for (int j = 0; j < 32; j++) {
        int c = cw * 32 + j;
        const float* xp = x + ((size_t)b * C_ + c) * HW_ + hw;
        float x0 = __ldg(xp);
        float x1 = __ldg(xp + (size_t)1*B_*C_*HW_);
        float x2 = __ldg(xp + (size_t)2*B_*C_*HW_);
        float x3 = __ldg(xp + (size_t)3*B_*C_*HW_);
        float v = 0.f, h;
        h = v + (x0 - v) * decay; if (h >= 1.0f) { bits[0] |= 1u << j; v = 0.f; } else v = h;
        h = v + (x1 - v) * decay; if (h >= 1.0f) { bits[1] |= 1u << j; v = 0.f; } else v = h;
        h = v + (x2 - v) * decay; if (h >= 1.0f) { bits[2] |= 1u << j; v = 0.f; } else v = h;
        h = v + (x3 - v) * decay; if (h >= 1.0f) { bits[3] |= 1u << j; v = 0.f; } else v = h;
    }
    #pragma unroll
    for (int t = 0; t < T_; t++)
        smask[p * T_ + t][cw] = bits[t];
    __syncthreads();

    const int lane = p;
    for (int r = cw; r < 128; r += CW_) {
        const int grow = blockIdx.x * 128 + r;
        unsigned short* lp = g_list + (size_t)grow * C_;
        int base = 0;
        #pragma unroll
        for (int w = 0; w < CW_; w++) {
            unsigned word = smask[r][w];
            if ((word >> lane) & 1u) {
                int pre = __popc(word & ((1u << lane) - 1u));
                lp[base + pre] = (unsigned short)(w * 32 + lane);
            }
            base += __popc(word);
        }
        int padded = (base + 7) & ~7;
        if (lane < padded - base) lp[base + lane] = (unsigned short)C_;
        if (lane == 0) g_cnt[grow] = base;
    }
}

// ---------------- K2: fused sparse GEMM1 (bf16 tile) + flagged PLIF2 ----------------
__device__ __forceinline__ void addx2(unsigned long long& a, unsigned long long v) {
    asm("add.rn.f32x2 %0, %0, %1;" : "+l"(a) : "l"(v));
}
// one visit: thread reads its 8B (4 bf16 = 4 outputs), expands, accumulates.
__device__ __forceinline__ void accb(unsigned long long& s01, unsigned long long& s23,
                                     unsigned wbase, unsigned c) {
    unsigned g0, g1;
    asm("ld.shared.v2.u32 {%0,%1},[%2];" : "=r"(g0), "=r"(g1) : "r"(wbase + c * 256u));
    unsigned long long d0, d1;
    asm("{\n\t.reg .b32 lo, hi;\n\t"
        "shl.b32 lo, %1, 16;\n\t"
        "and.b32 hi, %1, 0xffff0000;\n\t"
        "mov.b64 %0, {lo, hi};\n\t}" : "=l"(d0) : "r"(g0));
    asm("{\n\t.reg .b32 lo, hi;\n\t"
        "shl.b32 lo, %1, 16;\n\t"
        "and.b32 hi, %1, 0xffff0000;\n\t"
        "mov.b64 %0, {lo, hi};\n\t}" : "=l"(d1) : "r"(g1));
    addx2(s01, d0); addx2(s23, d1);
}

__global__ __launch_bounds__(1024, 1)
void k_gemm1_plif2(const float* __restrict__ pw2, const float* __restrict__ b1) {
    extern __shared__ char sm[];
    unsigned*       ws    = (unsigned*)sm;                       // [(C_+1)][ON] bf16
    unsigned short* slist = (unsigned short*)(sm + WS_BYTES);    // [RPG][LCAP]
    int*            scnt  = (int*)(sm + WS_BYTES + SL_BYTES);

    const int chunk = blockIdx.x;              // 0..NCH-1
    const int tid   = threadIdx.x;
    const int warp  = tid >> 5, oq = tid & 31;

    // stage w1t[:, chunk*ON:+ON] as bf16 (row C_ = zeros sentinel)
    const float* wp = g_w1t + chunk * ON;
    for (int i = tid; i < (C_ + 1) * (ON/4); i += 1024) {
        int c  = i >> 5;                       // ON/4 = 32
        int o4 = i & 31;
        float4 f = (c < C_) ? __ldg((const float4*)(wp + (size_t)c * HID_) + o4)
                            : make_float4(0.f, 0.f, 0.f, 0.f);
        __nv_bfloat162 p0 = __floats2bfloat162_rn(f.x, f.y);
        __nv_bfloat162 p1 = __floats2bfloat162_rn(f.z, f.w);
        unsigned lo, hi;
        memcpy(&lo, &p0, 4);
        memcpy(&hi, &p1, 4);
        ((uint2*)ws)[i] = make_uint2(lo, hi);
    }

    const unsigned wbase = (unsigned)__cvta_generic_to_shared(ws) + oq * 8u;
    const float decay = 1.0f / (1.0f + expf(-pw2[0]));
    const float4 b1v = __ldg((const float4*)(b1 + chunk * ON) + oq);
    const int obase = chunk * ON + oq * 4;

    for (int g = blockIdx.y; g < NG; g += GSPLIT) {
        const int row0 = g * RPG;
        __syncthreads();                       // weights staged / prev group done

        {   // stage lists (64 entries = 128B/row) + counts
            const uint4* gl4 = (const uint4*)(g_list + (size_t)row0 * C_);
            uint4*       sl4 = (uint4*)slist;
            for (int i = tid; i < RPG * (LCAP/8); i += 1024)
                sl4[i] = gl4[(size_t)(i >> 3) * (C_/8) + (i & 7)];
            if (tid < RPG) scnt[tid] = g_cnt[row0 + tid];
        }
        __syncthreads();

        #pragma unroll
        for (int p = 0; p < 2; p++) {
            const int lpair = warp * 2 + p;
            const int pair  = g * PG + lpair;

            unsigned long long A01[T_], A23[T_];
            #pragma unroll
            for (int t = 0; t < T_; t++) { A01[t] = 0ull; A23[t] = 0ull; }

            #pragma unroll
            for (int t = 0; t < T_; t++) {
                const int lr = lpair * T_ + t;
                const int n  = scnt[lr];
                const uint4* lp = (const uint4*)(slist + lr * LCAP);
                unsigned long long s01 = 0ull, s23 = 0ull;
                const int nc = n < LCAP ? n : LCAP;
                const int trips = (nc + 7) >> 3;
                for (int q = 0; q < trips; q++) {
                    uint4 L = lp[q];                       // broadcast LDS
                    accb(s01, s23, wbase, L.x & 0xffffu);
                    accb(s01, s23, wbase, L.x >> 16);
                    accb(s01, s23, wbase, L.y & 0xffffu);
                    accb(s01, s23, wbase, L.y >> 16);
                    accb(s01, s23, wbase, L.z & 0xffffu);
                    accb(s01, s23, wbase, L.z >> 16);
                    accb(s01, s23, wbase, L.w & 0xffffu);
                    accb(s01, s23, wbase, L.w >> 16);
                }
                if (n > LCAP) {                             // very rare tail
                    const unsigned short* gp = g_list + (size_t)(row0 + lr) * C_;
                    for (int j = LCAP; j < n; j++)
                        accb(s01, s23, wbase, (unsigned)gp[j]);
                }
                A01[t] = s01; A23[t] = s23;
            }

            // PLIF2 epilogue with certified flagging
            const int b = pair / HW_, hw = pair % HW_;
            #pragma unroll
            for (int j = 0; j < 4; j++) {
                const int o = obase + j;
                const float bb = (&b1v.x)[j];
                float v = 0.f;
                bool flag = false;
                int sb = 0;
                #pragma unroll
                for (int t = 0; t < T_; t++) {
                    unsigned long long aw = (j < 2) ? A01[t] : A23[t];
                    float a = __uint_as_float((j & 1) ? (unsigned)(aw >> 32)
                                                      : (unsigned)aw);
                    float xx = a + bb;
                    float h = v + (xx - v) * decay;
                    flag |= (fabsf(h - 1.0f) < DELTA);
                    if (h >= 1.0f) { sb |= 1 << t; v = 0.f; } else v = h;
                }
                if (flag) {
                    unsigned pos = atomicAdd(&g_nfix, 1u);
                    if (pos < FIX_CAP) g_fix[pos] = ((unsigned)pair << 11) | (unsigned)o;
                } else if (sb) {
                    #pragma unroll
                    for (int t = 0; t < T_; t++) if ((sb >> t) & 1) {
                        unsigned pos = atomicAdd(&g_nspk, 1u);
                        if (pos < SPIKE_CAP)
                            g_spikes[pos] = (unsigned)((((t * B_ + b) * HID_) + o) * HW_ + hw);
                    }
                }
            }
        }
    }
}

// ---------------- K3: exact fp32 fixup for flagged elements ----------------
__global__ void k_fixup(const float* __restrict__ pw2, const float* __restrict__ b1) {
    unsigned n = *(volatile unsigned*)&g_nfix;
    if (n > FIX_CAP) n = FIX_CAP;
    const float decay = 1.0f / (1.0f + expf(-pw2[0]));
    for (unsigned i = blockIdx.x * blockDim.x + threadIdx.x; i < n;
         i += gridDim.x * blockDim.x) {
        unsigned e = g_fix[i];
        int pair = e >> 11;
        int o    = e & 2047;
        int b = pair / HW_, hw = pair % HW_;
        float bb = __ldg(b1 + o);
        float v = 0.f;
        #pragma unroll
        for (int t = 0; t < T_; t++) {
            int row = pair * T_ + t;
            int cnt = g_cnt[row];
            const unsigned short* lp = g_list + (size_t)row * C_;
            float s = 0.f;
            for (int j = 0; j < cnt; j++)
                s += __ldg(g_w1t + (size_t)lp[j] * HID_ + o);
            float xx = s + bb;
            float h = v + (xx - v) * decay;
            if (h >= 1.0f) {
                unsigned pos = atomicAdd(&g_nspk, 1u);
                if (pos < SPIKE_CAP)
                    g_spikes[pos] = (unsigned)((((t * B_ + b) * HID_) + o) * HW_ + hw);
                v = 0.f;
            } else v = h;
        }
    }
}

// ---------------- K4: out = b2 ----------------
__global__ __launch_bounds__(256)
void k_outinit(float* __restrict__ out, const float* __restrict__ b2) {
    const int total4 = T_ * B_ * C_ * HW_ / 4;
    int base = (blockIdx.x * blockDim.x + threadIdx.x) * 2;
    #pragma unroll
    for (int k = 0; k < 2; k++) {
        int idx = base + k;
        if (idx < total4) {
            int o = (idx / (HW_ / 4)) % C_;
            float bv = __ldg(b2 + o);
            ((float4*)out)[idx] = make_float4(bv, bv, bv, bv);
        }
    }
}

// ---------------- K5: scatter spikes ----------------
__global__ void k_scatter(float* __restrict__ out) {
    unsigned n = *(volatile unsigned*)&g_nspk;
    if (n > SPIKE_CAP) n = SPIKE_CAP;
    int wid  = (blockIdx.x * blockDim.x + threadIdx.x) >> 5;
    int lane = threadIdx.x & 31;
    int nw   = (gridDim.x * blockDim.x) >> 5;
    for (unsigned s = wid; s < n; s += nw) {
        unsigned lin = g_spikes[s];
        unsigned hw = lin % HW_;
        unsigned r  = lin / HW_;
        unsigned c  = r % HID_;
        unsigned tb = r / HID_;
        const float* wcol = g_w2t + (size_t)c * C_;
        float* op = out + (size_t)tb * C_ * HW_ + hw;
        for (int o = lane; o < C_; o += 32)
            atomicAdd(op + (size_t)o * HW_, wcol[o]);
    }
}

// ---------------- launch ----------------
extern "C" void kernel_launch(void* const* d_in, const int* in_sizes, int n_in,
                              void* d_out, int out_size) {
    const float* x   = (const float*)d_in[0];
    const float* pw1 = (const float*)d_in[1];
    const float* w1  = (const float*)d_in[2];
    const float* b1  = (const float*)d_in[3];
    const float* pw2 = (const float*)d_in[4];
    const float* w2  = (const float*)d_in[5];
    const float* b2  = (const float*)d_in[6];
    float* out = (float*)d_out;
    (void)in_sizes; (void)n_in; (void)out_size;

    cudaFuncSetAttribute(k_gemm1_plif2,
                         cudaFuncAttributeMaxDynamicSharedMemorySize, SMEM2);

    {   // both transposes + counter reset
        dim3 blk(32, 8), grd(48, 48, 2);
        k_transpose_both<<<grd, blk>>>(w1, w2);
    }

    k_plif1_list<<<NPAIR / 32, 384>>>(x, pw1);

    dim3 g2(NCH, GSPLIT);
    k_gemm1_plif2<<<g2, 1024, SMEM2>>>(pw2, b1);

    k_fixup<<<4, 256>>>(pw2, b1);

    const int total4 = T_ * B_ * C_ * HW_ / 4;
    k_outinit<<<(total4 / 2 + 255) / 256, 256>>>(out, b2);
    k_scatter<<<256, 256>>>(out);
}

// round 8
// speedup vs baseline: 1.1158x; 1.0503x over previous
#include <cuda_runtime.h>
#include <cuda_bf16.h>
#include <cstdint>
#include <cstring>

#define T_    4
#define B_    32
#define C_    384
#define HID_  1536
#define HW_   196
#define NPAIR (B_*HW_)        // 6272
#define NROW  (NPAIR*T_)      // 25088
#define CW_   (C_/32)         // 12
#define SPIKE_CAP (1u<<22)
#define FIX_CAP   (1u<<20)

#define ON2   256             // output-channel chunk (bf16 tile)
#define NCH2  (HID_/ON2)      // 6
#define CPC2  24              // CTAs per chunk: 6*24 = 144 = one wave
#define PG    32              // pairs per group
#define RPG   (PG*T_)         // 128 rows per group
#define NG    (NPAIR/PG)      // 196 groups
#define LCAP  64
#define EBK   0.0125f         // per-term certified relative error (2^-7 junk + 2^-8 quant + slack)

#define WS_BYTES ((C_+1)*ON2*2)    // 197120 (row C_ = zero sentinel)
#define SL_BYTES (RPG*LCAP*2)      // 16384
#define SC_BYTES (RPG*4)           // 512
#define SMEM2    (WS_BYTES + SL_BYTES + SC_BYTES + 16)   // 214032

// ---- static device scratch ----
__device__ float          g_w1t[C_*HID_];          // [c][o] fp32 (exact path)
__device__ float          g_w2t[HID_*C_];
__device__ unsigned short g_list[(size_t)NROW*C_]; // padded to mult-8 with sentinel C_
__device__ int            g_cnt[NROW];
__device__ unsigned       g_spikes[SPIKE_CAP];
__device__ unsigned       g_nspk;
__device__ unsigned       g_fix[FIX_CAP];
__device__ unsigned       g_nfix;
__device__ int            g_grpctr[NCH2];
__device__ unsigned       g_wmax;                  // bits of max|w1| (monotonic, same data every launch)

// ---------------- K0: both transposes + wmax + counter reset ----------------
__global__ void k_transpose_both(const float* __restrict__ w1, const float* __restrict__ w2) {
    if (blockIdx.x == 0 && blockIdx.y == 0 && blockIdx.z == 0 &&
        threadIdx.x == 0 && threadIdx.y == 0) {
        g_nspk = 0u; g_nfix = 0u;
        #pragma unroll
        for (int i = 0; i < NCH2; i++) g_grpctr[i] = 0;
    }
    const float* in; float* outp; int rows, cols;
    if (blockIdx.z == 0) { in = w1; outp = g_w1t; rows = HID_; cols = C_; }
    else                 { in = w2; outp = g_w2t; rows = C_;  cols = HID_; }
    int bx = blockIdx.x * 32, by = blockIdx.y * 32;
    if (bx >= cols || by >= rows) return;

    __shared__ float tile[32][33];
    int x = bx + threadIdx.x;
    float lm = 0.f;
    #pragma unroll
    for (int k = 0; k < 32; k += 8) {
        int y = by + threadIdx.y + k;
        if (x < cols && y < rows) {
            float val = in[(size_t)y*cols + x];
            tile[threadIdx.y + k][threadIdx.x] = val;
            lm = fmaxf(lm, fabsf(val));
        }
    }
    if (blockIdx.z == 0) {   // track max|w1|
        unsigned r = __reduce_max_sync(0xffffffffu, __float_as_uint(lm));
        if (threadIdx.x == 0) atomicMax(&g_wmax, r);
    }
    __syncthreads();
    int xo = by + threadIdx.x;
    #pragma unroll
    for (int k = 0; k < 32; k += 8) {
        int yo = bx + threadIdx.y + k;
        if (xo < rows && yo < cols)
            outp[(size_t)yo*rows + xo] = tile[threadIdx.x][threadIdx.y + k];
    }
}

// ---------------- K1: fused PLIF1 + list build (exact fp32) ----------------
__global__ __launch_bounds__(384)
void k_plif1_list(const float* __restrict__ x, const float* __restrict__ pw1) {
    __shared__ unsigned smask[128][CW_];
    const int tid  = threadIdx.x;
    const int p    = tid & 31;
    const int cw   = tid >> 5;
    const int pair = blockIdx.x * 32 + p;
    const int b = pair / HW_, hw = pair % HW_;
    const float decay = 1.0f / (1.0f + expf(-pw1[0]));

    unsigned bits[T_] = {0u, 0u, 0u, 0u};
    #pragma unroll 4
    for (int j = 0; j < 32; j++) {
        int c = cw * 32 + j;
        const float* xp = x + ((size_t)b * C_ + c) * HW_ + hw;
        float x0 = __ldg(xp);
        float x1 = __ldg(xp + (size_t)1*B_*C_*HW_);
        float x2 = __ldg(xp + (size_t)2*B_*C_*HW_);
        float x3 = __ldg(xp + (size_t)3*B_*C_*HW_);
        float v = 0.f, h;
        h = v + (x0 - v) * decay; if (h >= 1.0f) { bits[0] |= 1u << j; v = 0.f; } else v = h;
        h = v + (x1 - v) * decay; if (h >= 1.0f) { bits[1] |= 1u << j; v = 0.f; } else v = h;
        h = v + (x2 - v) * decay; if (h >= 1.0f) { bits[2] |= 1u << j; v = 0.f; } else v = h;
        h = v + (x3 - v) * decay; if (h >= 1.0f) { bits[3] |= 1u << j; v = 0.f; } else v = h;
    }
    #pragma unroll
    for (int t = 0; t < T_; t++)
        smask[p * T_ + t][cw] = bits[t];
    __syncthreads();

    const int lane = p;
    for (int r = cw; r < 128; r += CW_) {
        const int grow = blockIdx.x * 128 + r;
        unsigned short* lp = g_list + (size_t)grow * C_;
        int base = 0;
        #pragma unroll
        for (int w = 0; w < CW_; w++) {
            unsigned word = smask[r][w];
            if ((word >> lane) & 1u) {
                int pre = __popc(word & ((1u << lane) - 1u));
                lp[base + pre] = (unsigned short)(w * 32 + lane);
            }
            base += __popc(word);
        }
        int padded = (base + 7) & ~7;
        if (lane < padded - base) lp[base + lane] = (unsigned short)C_;
        if (lane == 0) g_cnt[grow] = base;
    }
}

// ---------------- K2: fused sparse GEMM1 (bf16 junk-tolerant) + certified PLIF2 ----------------
__device__ __forceinline__ void addx2(unsigned long long& a, unsigned long long v) {
    asm("add.rn.f32x2 %0, %0, %1;" : "+l"(a) : "l"(v));
}
// one visit: 8B = 2 bf16-pairs = 4 outputs.  sa accumulates even outputs (exact
// shifted bf16); sb accumulates odd outputs as raw u32-as-fp32 (junk <= 2^-7 rel).
__device__ __forceinline__ void accv(unsigned long long& sa, unsigned long long& sb,
                                     unsigned addr) {
    unsigned g0, g1;
    asm("ld.shared.v2.u32 {%0,%1},[%2];" : "=r"(g0), "=r"(g1) : "r"(addr));
    unsigned long long da, db;
    asm("{\n\t.reg .b32 l0,l1;\n\t"
        "shl.b32 l0,%1,16;\n\t"
        "shl.b32 l1,%2,16;\n\t"
        "mov.b64 %0,{l0,l1};\n\t}" : "=l"(da) : "r"(g0), "r"(g1));
    asm("mov.b64 %0,{%1,%2};" : "=l"(db) : "r"(g0), "r"(g1));
    addx2(sa, da); addx2(sb, db);
}

__global__ __launch_bounds__(1024, 1)
void k_gemm1_plif2(const float* __restrict__ pw2, const float* __restrict__ b1) {
    extern __shared__ char sm[];
    unsigned short* ws    = (unsigned short*)sm;                 // [(C_+1)][ON2] bf16
    unsigned short* slist = (unsigned short*)(sm + WS_BYTES);    // [RPG][LCAP]
    int*            scnt  = (int*)(sm + WS_BYTES + SL_BYTES);    // [RPG]
    int*            s_g   = (int*)(sm + WS_BYTES + SL_BYTES + SC_BYTES);

    const int chunk = blockIdx.x;              // 0..NCH2-1
    const int tid   = threadIdx.x;
    const int warp  = tid >> 5, oq = tid & 31;
    const int slot  = warp >> 1;               // pair slot 0..15
    const int hf    = warp & 1;                // which 128-output half

    // stage w1t[:, chunk*ON2:+ON2] as bf16 once (row C_ = zeros sentinel)
    const float* wp = g_w1t + chunk * ON2;
    for (int i = tid; i < (C_ + 1) * (ON2/4); i += 1024) {
        int c  = i >> 6;                       // ON2/4 = 64
        int o4 = i & 63;
        float4 f = (c < C_) ? __ldg((const float4*)(wp + (size_t)c * HID_) + o4)
                            : make_float4(0.f, 0.f, 0.f, 0.f);
        __nv_bfloat162 p0 = __floats2bfloat162_rn(f.x, f.y);
        __nv_bfloat162 p1 = __floats2bfloat162_rn(f.z, f.w);
        unsigned lo, hi;
        memcpy(&lo, &p0, 4); memcpy(&hi, &p1, 4);
        ((uint2*)ws)[i] = make_uint2(lo, hi);
    }

    const unsigned wbase = (unsigned)__cvta_generic_to_shared(ws) + hf * 256u + oq * 8u;
    const float decay = 1.0f / (1.0f + expf(-pw2[0]));
    const float ebn = EBK * __uint_as_float(*(volatile unsigned*)&g_wmax);
    const float4 b1v = __ldg((const float4*)(b1 + chunk * ON2) + (hf * 32 + oq));
    const int obase = chunk * ON2 + hf * 128 + oq * 4;

    for (;;) {
        __syncthreads();                       // prev group compute done / weights staged
        if (tid == 0) *s_g = atomicAdd(&g_grpctr[chunk], 1);
        __syncthreads();
        const int g = *s_g;
        if (g >= NG) break;
        const int row0 = g * RPG;

        {   // stage lists: 128 rows x 64 entries = 1024 uint4, one per thread
            const uint4* gl4 = (const uint4*)(g_list + (size_t)row0 * C_);
            ((uint4*)slist)[tid] = gl4[(size_t)(tid >> 3) * (C_/8) + (tid & 7)];
            if (tid < RPG) scnt[tid] = g_cnt[row0 + tid];
        }
        __syncthreads();

        #pragma unroll
        for (int p = 0; p < 2; p++) {
            const int lpair = slot * 2 + p;            // 0..31
            const int pair  = g * PG + lpair;
            const int4 cn = *(const int4*)(scnt + lpair * 4);

            unsigned long long SA[T_], SB[T_];
            #pragma unroll
            for (int t = 0; t < T_; t++) { SA[t] = 0ull; SB[t] = 0ull; }

            #pragma unroll
            for (int t = 0; t < T_; t++) {
                const int n = (&cn.x)[t];
                const int lr = lpair * T_ + t;
                const uint4* lp = (const uint4*)(slist + lr * LCAP);
                unsigned long long sa = 0ull, sb = 0ull;
                const int nc = n < LCAP ? n : LCAP;
                const int trips = (nc + 7) >> 3;
                for (int q = 0; q < trips; q++) {
                    uint4 L = lp[q];                   // broadcast LDS
                    accv(sa, sb, wbase + (L.x & 0xffffu) * 512u);
                    accv(sa, sb, wbase + (L.x >> 16)     * 512u);
                    accv(sa, sb, wbase + (L.y & 0xffffu) * 512u);
                    accv(sa, sb, wbase + (L.y >> 16)     * 512u);
                    accv(sa, sb, wbase + (L.z & 0xffffu) * 512u);
                    accv(sa, sb, wbase + (L.z >> 16)     * 512u);
                    accv(sa, sb, wbase + (L.w & 0xffffu) * 512u);
                    accv(sa, sb, wbase + (L.w >> 16)     * 512u);
                }
                if (n > LCAP) {                         // extremely rare tail
                    const unsigned short* gp = g_list + (size_t)(row0 + lr) * C_;
                    for (int j = LCAP; j < n; j++)
                        accv(sa, sb, wbase + (unsigned)gp[j] * 512u);
                }
                SA[t] = sa; SB[t] = sb;
            }

            // PLIF2 epilogue with certified error recurrence
            const int b = pair / HW_, hw = pair % HW_;
            #pragma unroll
            for (int j = 0; j < 4; j++) {
                const int o = obase + j;
                const float bb = (&b1v.x)[j];
                float v = 0.f, e = 0.f;
                bool flag = false;
                int sb_bits = 0;
                #pragma unroll
                for (int t = 0; t < T_; t++) {
                    unsigned long long aw = (j & 1) ? SB[t] : SA[t];
                    float a = __uint_as_float((j < 2) ? (unsigned)aw
                                                      : (unsigned)(aw >> 32));
                    float xx = a + bb;
                    float h = v + (xx - v) * decay;
                    float en = (1.0f - decay) * e + decay * ebn * (float)((&cn.x)[t]);
                    if (fabsf(h - 1.0f) <= en) flag = true;
                    if (h >= 1.0f) { sb_bits |= 1 << t; v = 0.f; e = 0.f; }
                    else           { v = h; e = en; }
                }
                if (flag) {
                    unsigned pos = atomicAdd(&g_nfix, 1u);
                    if (pos < FIX_CAP) g_fix[pos] = ((unsigned)pair << 11) | (unsigned)o;
                } else if (sb_bits) {
                    #pragma unroll
                    for (int t = 0; t < T_; t++) if ((sb_bits >> t) & 1) {
                        unsigned pos = atomicAdd(&g_nspk, 1u);
                        if (pos < SPIKE_CAP)
                            g_spikes[pos] = (unsigned)((((t * B_ + b) * HID_) + o) * HW_ + hw);
                    }
                }
            }
        }
    }
}

// ---------------- K3: exact fp32 fixup (same sum order as exact path) ----------------
__global__ void k_fixup(const float* __restrict__ pw2, const float* __restrict__ b1) {
    unsigned n = *(volatile unsigned*)&g_nfix;
    if (n > FIX_CAP) n = FIX_CAP;
    const float decay = 1.0f / (1.0f + expf(-pw2[0]));
    for (unsigned i = blockIdx.x * blockDim.x + threadIdx.x; i < n;
         i += gridDim.x * blockDim.x) {
        unsigned ecode = g_fix[i];
        int pair = ecode >> 11;
        int o    = ecode & 2047;
        int b = pair / HW_, hw = pair % HW_;
        float bb = __ldg(b1 + o);
        float v = 0.f;
        #pragma unroll
        for (int t = 0; t < T_; t++) {
            int row = pair * T_ + t;
            int cnt = g_cnt[row];
            const unsigned short* lp = g_list + (size_t)row * C_;
            float s = 0.f;
            for (int j = 0; j < cnt; j++)
                s += __ldg(g_w1t + (size_t)lp[j] * HID_ + o);
            float xx = s + bb;
            float h = v + (xx - v) * decay;
            if (h >= 1.0f) {
                unsigned pos = atomicAdd(&g_nspk, 1u);
                if (pos < SPIKE_CAP)
                    g_spikes[pos] = (unsigned)((((t * B_ + b) * HID_) + o) * HW_ + hw);
                v = 0.f;
            } else v = h;
        }
    }
}

// ---------------- K4: out = b2 (division-free slab fill) ----------------
__global__ __launch_bounds__(256)
void k_outinit(float* __restrict__ out, const float* __restrict__ b2) {
    int s = blockIdx.x * 4 + (threadIdx.x >> 6);     // channel-slab in [0, T*B*C)
    int q = threadIdx.x & 63;
    float bv = __ldg(b2 + (s % C_));
    if (q < HW_/4) {
        ((float4*)out)[(size_t)s * (HW_/4) + q] = make_float4(bv, bv, bv, bv);
    }
}

// ---------------- K5: scatter spikes ----------------
__global__ void k_scatter(float* __restrict__ out) {
    unsigned n = *(volatile unsigned*)&g_nspk;
    if (n > SPIKE_CAP) n = SPIKE_CAP;
    int wid  = (blockIdx.x * blockDim.x + threadIdx.x) >> 5;
    int lane = threadIdx.x & 31;
    int nw   = (gridDim.x * blockDim.x) >> 5;
    for (unsigned s = wid; s < n; s += nw) {
        unsigned lin = g_spikes[s];
        unsigned hw = lin % HW_;
        unsigned r  = lin / HW_;
        unsigned c  = r % HID_;
        unsigned tb = r / HID_;
        const float* wcol = g_w2t + (size_t)c * C_;
        float* op = out + (size_t)tb * C_ * HW_ + hw;
        for (int o = lane; o < C_; o += 32)
            atomicAdd(op + (size_t)o * HW_, wcol[o]);
    }
}

// ---------------- launch ----------------
extern "C" void kernel_launch(void* const* d_in, const int* in_sizes, int n_in,
                              void* d_out, int out_size) {
    const float* x   = (const float*)d_in[0];
    const float* pw1 = (const float*)d_in[1];
    const float* w1  = (const float*)d_in[2];
    const float* b1  = (const float*)d_in[3];
    const float* pw2 = (const float*)d_in[4];
    const float* w2  = (const float*)d_in[5];
    const float* b2  = (const float*)d_in[6];
    float* out = (float*)d_out;
    (void)in_sizes; (void)n_in; (void)out_size;

    cudaFuncSetAttribute(k_gemm1_plif2,
                         cudaFuncAttributeMaxDynamicSharedMemorySize, SMEM2);

    {   // both transposes + wmax + counter reset
        dim3 blk(32, 8), grd(48, 48, 2);
        k_transpose_both<<<grd, blk>>>(w1, w2);
    }

    k_plif1_list<<<NPAIR / 32, 384>>>(x, pw1);

    dim3 g2(NCH2, CPC2);
    k_gemm1_plif2<<<g2, 1024, SMEM2>>>(pw2, b1);

    k_fixup<<<32, 256>>>(pw2, b1);

    k_outinit<<<(T_ * B_ * C_) / 4, 256>>>(out, b2);
    k_scatter<<<256, 256>>>(out);
}